// round 16
// baseline (speedup 1.0000x reference)
#include <cuda_runtime.h>
#include <cuda_bf16.h>
#include <cstdint>

#define TT   256
#define BB   64
#define II   512
#define HH   1024
#define SBUF (3 * BB * HH)
#define BH   (BB * HH)

#define A_CH 8192
#define B_CH 16384
#define NCH0 40
#define NCH1 48
#define NCH2 32

#define WIMG_L0 0ULL
#define WIMG_L1 (WIMG_L0 + 128ULL * NCH0 * A_CH)
#define WIMG_L2 (WIMG_L1 + 128ULL * NCH1 * A_CH)
#define WIMG_TOT (WIMG_L2 + 128ULL * NCH2 * A_CH)

#define STG_BYTES 24576            // A 8KB + B 16KB per stage
#define NSTG 8                     // 4 pair-slots
#define SMEM_DYN (NSTG * STG_BYTES)

__device__ __align__(16) char g_wimg[WIMG_TOT];
__device__ __align__(16) char g_ximg[(size_t)TT * 8 * B_CH];
__device__ __align__(16) char g_himg[2][3][16 * B_CH];
__device__ float g_h[2 * SBUF];    // SORTED batch order
__device__ float g_c[2 * SBUF];
__device__ int   g_len[BB];        // sorted desc
__device__ int   g_perm[BB];       // sorted idx -> real b
__device__ int   g_mcnt[TT];       // m(t) = #(len > t)

__device__ __forceinline__ uint32_t smem_u32(const void* p) {
    uint32_t a;
    asm("{ .reg .u64 t; cvta.to.shared.u64 t, %1; cvt.u32.u64 %0, t; }" : "=r"(a) : "l"(p));
    return a;
}
__device__ __forceinline__ float sigf(float x) { return 1.0f / (1.0f + __expf(-x)); }
__device__ __forceinline__ uint16_t bf16bits(float v) {
    __nv_bfloat16 b = __float2bfloat16(v);
    return *(uint16_t*)&b;
}
__device__ __forceinline__ float bf16val(uint16_t u) {
    __nv_bfloat16 b = *(__nv_bfloat16*)&u;
    return __bfloat162float(b);
}
__device__ __forceinline__ uint32_t pack_split(float v0, float v1, int split) {
    uint16_t h0 = bf16bits(v0), h1 = bf16bits(v1);
    if (split == 0) return (uint32_t)h0 | ((uint32_t)h1 << 16);
    uint16_t l0 = bf16bits(v0 - bf16val(h0)), l1 = bf16bits(v1 - bf16val(h1));
    return (uint32_t)l0 | ((uint32_t)l1 << 16);
}

#define MMA(c, a, b) \
    asm volatile("mma.sync.aligned.m16n8k16.row.col.f32.bf16.bf16.f32 " \
        "{%0,%1,%2,%3}, {%4,%5,%6,%7}, {%8,%9}, {%0,%1,%2,%3};" \
        : "+f"((c)[0]), "+f"((c)[1]), "+f"((c)[2]), "+f"((c)[3]) \
        : "r"((a).x), "r"((a).y), "r"((a).z), "r"((a).w), "r"((b).x), "r"((b).y))

#define CPA16(dst, src) \
    asm volatile("cp.async.cg.shared.global [%0], [%1], 16;" :: "r"(dst), "l"(src))

template<int NFB>
__device__ __forceinline__ void mma_body(
    const char* __restrict__ base, int jsub, int ksub, int bhalf, int lane,
    float (&acc)[4][3][4])
{
    const char* Ab = base + jsub * 1024 + lane * 16;
    const char* Bb = base + 8192 + bhalf * 2048 + lane * 8;
#pragma unroll
    for (int kk = 0; kk < 2; kk++) {
        const int k16 = ksub * 2 + kk;
        const uint4 ah = *(const uint4*)(Ab + k16 * 2048);
        const uint4 al = *(const uint4*)(Ab + k16 * 2048 + 512);
#pragma unroll
        for (int nf = 0; nf < NFB; nf++) {
            const uint2 bh = *(const uint2*)(Bb + k16 * 4096 + nf * 256);
            const uint2 bl = *(const uint2*)(Bb + k16 * 4096 + 1024 + nf * 256);
            MMA(acc[nf][0], ah, bh);
            MMA(acc[nf][1], ah, bl);
            MMA(acc[nf][2], al, bh);
        }
    }
}

// ---------------- prep kernels (same as R15) ----------------
__global__ void prep_sort(const void* lenbuf) {
    if (threadIdx.x != 0 || blockIdx.x != 0) return;
    const long long* L64 = (const long long*)lenbuf;
    const int*       L32 = (const int*)lenbuf;
    bool is64 = true;
    for (int b = 0; b < 32; b++) {
        long long v = L64[b];
        if (v < 0 || v > TT) { is64 = false; break; }
    }
    int len[BB], idx[BB];
    for (int b = 0; b < BB; b++) { len[b] = is64 ? (int)L64[b] : L32[b]; idx[b] = b; }
    for (int i = 1; i < BB; i++) {
        int lv = len[i], iv = idx[i], j = i - 1;
        while (j >= 0 && len[j] < lv) { len[j + 1] = len[j]; idx[j + 1] = idx[j]; j--; }
        len[j + 1] = lv; idx[j + 1] = iv;
    }
    for (int b = 0; b < BB; b++) { g_len[b] = len[b]; g_perm[b] = idx[b]; }
    for (int t = 0; t < TT; t++) {
        int m = 0;
        while (m < BB && len[m] > t) m++;
        g_mcnt[t] = m;
    }
}

__global__ void __launch_bounds__(128) prep_misc(
    const float* __restrict__ h0, const float* __restrict__ c0)
{
    __shared__ float sa[64][68];
    const int q = blockIdx.x, o = blockIdx.y, tid = threadIdx.x;

    for (int i = (o * 16 + q) * 128 + tid; i < SBUF; i += 48 * 128) {
        int l = i >> 16, r = i & (BH - 1);
        int bs = r >> 10, n = r & (HH - 1);
        int src = l * BH + g_perm[bs] * HH + n;
        g_h[i] = h0[src]; g_c[i] = c0[src];
    }
    char* out = &g_himg[0][o][(size_t)q * B_CH];
    const int kb = q * 64;
#pragma unroll
    for (int r = 0; r < 8; r++) {
        int u = tid + 128 * r;
        int b = u >> 4, c4 = u & 15;
        const float4 v = *(const float4*)(h0 + ((size_t)o * BB + g_perm[b]) * HH + kb + c4 * 4);
        float* d = &sa[b][c4 * 4];
        d[0] = v.x; d[1] = v.y; d[2] = v.z; d[3] = v.w;
    }
    __syncthreads();
#pragma unroll
    for (int r = 0; r < 16; r++) {
        int u = tid + 128 * r;
        int lane = u & 31, rest = u >> 5;
        int nfrag = rest & 3, split = (rest >> 2) & 1, bgroup = (rest >> 3) & 1, k16 = rest >> 4;
        int g = lane >> 2, tig = lane & 3;
        int b = bgroup * 32 + nfrag * 8 + g;
        uint32_t regs[2];
#pragma unroll
        for (int kh = 0; kh < 2; kh++) {
            int k = k16 * 16 + 2 * tig + kh * 8;
            regs[kh] = pack_split(sa[b][k], sa[b][k + 1], split);
        }
        *(uint2*)(out + k16 * 4096 + bgroup * 2048 + split * 1024 + nfrag * 256 + lane * 8)
            = make_uint2(regs[0], regs[1]);
    }
}

struct WJobs {
    const float* W[8];
    unsigned long long off[8];
    int NCH[8];
    int so[8];
    int nq[8];
};
__global__ void __launch_bounds__(128) prep_w_all(WJobs jb, char* __restrict__ wimg) {
    __shared__ float sw[64][36];
    const int jidx = blockIdx.z;
    const int q = blockIdx.x, jt = blockIdx.y, tid = threadIdx.x;
    if (q >= jb.nq[jidx]) return;
    const float* __restrict__ W = jb.W[jidx];
    char* out = wimg + jb.off[jidx] + ((size_t)jt * jb.NCH[jidx] + jb.so[jidx] + q) * A_CH;
    const int kb = q * 64;

#pragma unroll
    for (int r = 0; r < 4; r++) {
        int u = tid + 128 * r;
        int k = u >> 3, rem = u & 7, gate = rem >> 1, pair = rem & 1;
        const float4 v = *(const float4*)(W + (size_t)(kb + k) * 4096 + gate * 1024 + jt * 8 + pair * 4);
        float* d = &sw[k][gate * 8 + pair * 4];
        d[0] = v.x; d[1] = v.y; d[2] = v.z; d[3] = v.w;
    }
    __syncthreads();
#pragma unroll
    for (int r = 0; r < 4; r++) {
        int u = tid + 128 * r;
        int lane = u & 31, rest = u >> 5;
        int split = rest & 1, jsub = (rest >> 1) & 1, k16 = rest >> 2;
        int g = lane >> 2, tig = lane & 3;
        uint32_t regs[4];
#pragma unroll
        for (int rg = 0; rg < 4; rg++) {
            int col = jsub * 16 + (rg & 1) * 8 + g;
            int kx  = k16 * 16 + 2 * tig + (rg >> 1) * 8;
            regs[rg] = pack_split(sw[kx][col], sw[kx + 1][col], split);
        }
        *(uint4*)(out + k16 * 2048 + jsub * 1024 + split * 512 + lane * 16)
            = make_uint4(regs[0], regs[1], regs[2], regs[3]);
    }
}

__global__ void __launch_bounds__(128) prep_x_kernel(const float* __restrict__ src) {
    __shared__ float sa[64][68];
    const int q = blockIdx.x, o = blockIdx.y, tid = threadIdx.x;
    const int kb = q * 64;
    char* out = g_ximg + ((size_t)o * 8 + q) * B_CH;

#pragma unroll
    for (int r = 0; r < 8; r++) {
        int u = tid + 128 * r;
        int b = u >> 4, c4 = u & 15;
        const float4 v = *(const float4*)(src + ((size_t)o * BB + g_perm[b]) * II + kb + c4 * 4);
        float* d = &sa[b][c4 * 4];
        d[0] = v.x; d[1] = v.y; d[2] = v.z; d[3] = v.w;
    }
    __syncthreads();
#pragma unroll
    for (int r = 0; r < 16; r++) {
        int u = tid + 128 * r;
        int lane = u & 31, rest = u >> 5;
        int nfrag = rest & 3, split = (rest >> 2) & 1, bgroup = (rest >> 3) & 1, k16 = rest >> 4;
        int g = lane >> 2, tig = lane & 3;
        int b = bgroup * 32 + nfrag * 8 + g;
        uint32_t regs[2];
#pragma unroll
        for (int kh = 0; kh < 2; kh++) {
            int k = k16 * 16 + 2 * tig + kh * 8;
            regs[kh] = pack_split(sa[b][k], sa[b][k + 1], split);
        }
        *(uint2*)(out + k16 * 4096 + bgroup * 2048 + split * 1024 + nfrag * 256 + lane * 8)
            = make_uint2(regs[0], regs[1]);
    }
}

// ---------------- fused HMMA LSTM: 1 or 2 independent layer-tasks per launch ----------------
struct LTask {
    const char* wimg;   // layer weight image base (already at layer offset)
    int nch;
    const char* bp0; int nq0;
    const char* bp1; int nq1;
    const char* bp2; int nq2;
    const float* bias;
    const float* cprev; const float* hprev;
    float* cout; float* hout;
    char* himg; float* outp;
    int t;
};

__device__ __forceinline__ const char* bsrcT(const LTask& T, int i) {
    if (i < T.nq0) return T.bp0 + (size_t)i * B_CH;
    i -= T.nq0;
    if (i < T.nq1) return T.bp1 + (size_t)i * B_CH;
    i -= T.nq1;
    return T.bp2 + (size_t)i * B_CH;
}

__global__ void __launch_bounds__(256, 1) lstm_fused(LTask A, LTask B, int two)
{
    extern __shared__ __align__(16) char sbuf[];   // 8 x [A 8KB | B 16KB]
    __shared__ float zsm[2][32][66];

    const int tid = threadIdx.x;
    const int lane = tid & 31, w = tid >> 5;
    const int jt = blockIdx.x;
    const int jsub = w >> 2, ksub = (w >> 1) & 1, bhalf = w & 1;
    const uint32_t sb = smem_u32(sbuf);

    const int nchA = A.nch;
    const int nchB = two ? B.nch : 0;
    const char* achA = A.wimg + (size_t)jt * nchA * A_CH;
    const char* achB = two ? (B.wimg + (size_t)jt * nchB * A_CH) : nullptr;

    const int bslot = (tid >> 7) * 32 + ((tid >> 4) & 3) * 8;   // b-block this thread copies

    const int mA = g_mcnt[A.t];
    int nfbA = (mA - bhalf * 32 + 7) >> 3;
    if (nfbA < 0) nfbA = 0; if (nfbA > 4) nfbA = 4;
    const bool bactA = bslot < mA;

    int mB = 0, nfbB = 0; bool bactB = false;
    if (two) {
        mB = g_mcnt[B.t];
        nfbB = (mB - bhalf * 32 + 7) >> 3;
        if (nfbB < 0) nfbB = 0; if (nfbB > 4) nfbB = 4;
        bactB = bslot < mB;
    }

    float acc[4][3][4];
#pragma unroll
    for (int f = 0; f < 4; f++)
#pragma unroll
        for (int s = 0; s < 3; s++)
#pragma unroll
            for (int e = 0; e < 4; e++) acc[f][s][e] = 0.0f;

    auto copy_chunk = [&](int ci) {                // no commit; caller groups
        const int stg = ci & 7;
        const char* aw; const char* sB; bool ba;
        if (ci < nchA) { aw = achA + (size_t)ci * A_CH; sB = bsrcT(A, ci); ba = bactA; }
        else { const int cl = ci - nchA; aw = achB + (size_t)cl * A_CH; sB = bsrcT(B, cl); ba = bactB; }
        const char* sA = aw + tid * 16;
        uint32_t dA = sb + stg * STG_BYTES + tid * 16;
        CPA16(dA, sA);
        CPA16(dA + 4096, sA + 4096);
        if (ba) {
            const char* sBB = sB + tid * 16;
            uint32_t dB = sb + stg * STG_BYTES + 8192 + tid * 16;
#pragma unroll
            for (int u = 0; u < 4; u++)
                CPA16(dB + u * 4096, sBB + u * 4096);
        }
    };
    auto copy_pair = [&](int p) {
        copy_chunk(2 * p);
        copy_chunk(2 * p + 1);
        asm volatile("cp.async.commit_group;" ::: "memory");
    };
    auto mma_sel = [&](int ci) {
        const char* base = sbuf + (ci & 7) * STG_BYTES;
        const int nfb = (ci < nchA) ? nfbA : nfbB;
        switch (nfb) {
            case 4: mma_body<4>(base, jsub, ksub, bhalf, lane, acc); break;
            case 3: mma_body<3>(base, jsub, ksub, bhalf, lane, acc); break;
            case 2: mma_body<2>(base, jsub, ksub, bhalf, lane, acc); break;
            case 1: mma_body<1>(base, jsub, ksub, bhalf, lane, acc); break;
            default: break;
        }
    };
    // Epilogue for task T using current acc; resets nothing. Uniform control flow.
    auto epilogue = [&](const LTask& T) {
        __syncthreads();                            // MMAs done; prior zsm reads done
        {
            const int g = lane >> 2, tig = lane & 3;
#pragma unroll
            for (int nf = 0; nf < 4; nf++) {
                const int bc = bhalf * 32 + nf * 8 + 2 * tig;
                float v0 = acc[nf][0][0] + acc[nf][1][0] + acc[nf][2][0];
                float v1 = acc[nf][0][1] + acc[nf][1][1] + acc[nf][2][1];
                float v2 = acc[nf][0][2] + acc[nf][1][2] + acc[nf][2][2];
                float v3 = acc[nf][0][3] + acc[nf][1][3] + acc[nf][2][3];
                zsm[ksub][jsub * 16 + g][bc]         = v0;
                zsm[ksub][jsub * 16 + g][bc + 1]     = v1;
                zsm[ksub][jsub * 16 + g + 8][bc]     = v2;
                zsm[ksub][jsub * 16 + g + 8][bc + 1] = v3;
            }
        }
        __syncthreads();

        const int ni = tid >> 5;
        const int bq = (tid & 31) * 2;
        const int ng = jt * 8 + ni;
        const float bfv = T.bias[ng], biv = T.bias[HH + ng];
        const float bov = T.bias[2 * HH + ng], bgv = T.bias[3 * HH + ng];

        const int k16h = (ng >> 4) & 3, kkh = ng & 15;
        const int tigh = (kkh >> 1) & 3, chh = kkh & 1, khalf = kkh >> 3;
        char* chb = T.himg + (size_t)(ng >> 6) * B_CH + k16h * 4096;
        const int inoff = khalf * 4 + chh * 2;

#pragma unroll
        for (int jb = 0; jb < 2; jb++) {
            const int b = bq + jb;
            const float zf = zsm[0][0 + ni][b]  + zsm[1][0 + ni][b]  + bfv;
            const float zi = zsm[0][8 + ni][b]  + zsm[1][8 + ni][b]  + biv;
            const float zo = zsm[0][16 + ni][b] + zsm[1][16 + ni][b] + bov;
            const float zg = zsm[0][24 + ni][b] + zsm[1][24 + ni][b] + bgv;
            const int sidx = b * HH + ng;
            const float cold = T.cprev[sidx], hold = T.hprev[sidx];

            float c1 = sigf(zf) * cold + sigf(zi) * tanhf(zg);
            float h1 = sigf(zo) * tanhf(c1);
            if (!(T.t < g_len[b])) { c1 = cold; h1 = hold; }

            T.cout[sidx] = c1;
            T.hout[sidx] = h1;
            if (T.outp) T.outp[(size_t)g_perm[b] * HH + ng] = h1;

            const int bloc = b & 31;
            char* p = chb + (b >> 5) * 2048 + (bloc >> 3) * 256 + ((bloc & 7) * 4 + tigh) * 8 + inoff;
            const uint16_t hb = bf16bits(h1);
            *(uint16_t*)p          = hb;
            *(uint16_t*)(p + 1024) = bf16bits(h1 - bf16val(hb));
        }
    };

    const int P  = (nchA + nchB) >> 1;             // all nch even -> pairs task-pure
    const int PA = nchA >> 1;
    copy_pair(0);
    if (P > 1) copy_pair(1);
    if (P > 2) copy_pair(2);

    for (int p = 0; p < P; p++) {
        const int rem = P - 1 - p;
        if (rem >= 2)      asm volatile("cp.async.wait_group 2;" ::: "memory");
        else if (rem == 1) asm volatile("cp.async.wait_group 1;" ::: "memory");
        else               asm volatile("cp.async.wait_group 0;" ::: "memory");
        __syncthreads();                           // pair p visible; pair p-1 slots free

        if (p + 3 < P) copy_pair(p + 3);

        mma_sel(2 * p);
        mma_sel(2 * p + 1);

        if (p == PA - 1) {                         // task A done: epilogue + reset acc
            epilogue(A);
#pragma unroll
            for (int f = 0; f < 4; f++)
#pragma unroll
                for (int s = 0; s < 3; s++)
#pragma unroll
                    for (int e = 0; e < 4; e++) acc[f][s][e] = 0.0f;
        }
    }
    if (two) epilogue(B);
}

__global__ void finalize_kernel(float* __restrict__ Hout, float* __restrict__ Cout) {
    int i = blockIdx.x * blockDim.x + threadIdx.x;
    if (i < SBUF) {                                // t=255 odd -> cur in buf 0; un-permute
        int l = i >> 16, r = i & (BH - 1);
        int bs = r >> 10, n = r & (HH - 1);
        int dst = l * BH + g_perm[bs] * HH + n;
        Hout[dst] = g_h[i];
        Cout[dst] = g_c[i];
    }
}

// ---------------- host ----------------
extern "C" void kernel_launch(void* const* d_in, const int* in_sizes, int n_in,
                              void* d_out, int out_size) {
    const float* x    = (const float*)d_in[0];
    const void*  len  = d_in[1];
    const float* h0   = (const float*)d_in[2];
    const float* c0   = (const float*)d_in[3];
    const float* Wbh0 = (const float*)d_in[4];
    const float* Whh0 = (const float*)d_in[5];
    const float* Wth0 = (const float*)d_in[6];
    const float* b0   = (const float*)d_in[7];
    const float* Wbh1 = (const float*)d_in[8];
    const float* Whh1 = (const float*)d_in[9];
    const float* Wth1 = (const float*)d_in[10];
    const float* b1   = (const float*)d_in[11];
    const float* Wih2 = (const float*)d_in[12];
    const float* Whh2 = (const float*)d_in[13];
    const float* b2   = (const float*)d_in[14];

    float* out  = (float*)d_out;
    float* Hout = out + (size_t)TT * BB * HH;
    float* Cout = Hout + SBUF;

    void* p;
    cudaGetSymbolAddress(&p, g_wimg); char*  Wimg = (char*)p;
    cudaGetSymbolAddress(&p, g_ximg); char*  Ximg = (char*)p;
    cudaGetSymbolAddress(&p, g_himg); char*  Himg = (char*)p;
    cudaGetSymbolAddress(&p, g_h);    float* Hs   = (float*)p;
    cudaGetSymbolAddress(&p, g_c);    float* Cs   = (float*)p;

    const size_t HIMG_L = 16 * B_CH;
    auto himg_at = [&](int pp, int layer) { return Himg + ((size_t)pp * 3 + layer) * HIMG_L; };

    cudaFuncSetAttribute(lstm_fused, cudaFuncAttributeMaxDynamicSharedMemorySize, SMEM_DYN);

    prep_sort<<<1, 32>>>(len);
    { dim3 g(16, 3); prep_misc<<<g, 128>>>(h0, c0); }
    WJobs jb;
    jb.W[0] = Whh0; jb.off[0] = WIMG_L0; jb.NCH[0] = NCH0; jb.so[0] = 0;  jb.nq[0] = 16;
    jb.W[1] = Wbh0; jb.off[1] = WIMG_L0; jb.NCH[1] = NCH0; jb.so[1] = 16; jb.nq[1] = 8;
    jb.W[2] = Wth0; jb.off[2] = WIMG_L0; jb.NCH[2] = NCH0; jb.so[2] = 24; jb.nq[2] = 16;
    jb.W[3] = Whh1; jb.off[3] = WIMG_L1; jb.NCH[3] = NCH1; jb.so[3] = 0;  jb.nq[3] = 16;
    jb.W[4] = Wbh1; jb.off[4] = WIMG_L1; jb.NCH[4] = NCH1; jb.so[4] = 16; jb.nq[4] = 16;
    jb.W[5] = Wth1; jb.off[5] = WIMG_L1; jb.NCH[5] = NCH1; jb.so[5] = 32; jb.nq[5] = 16;
    jb.W[6] = Whh2; jb.off[6] = WIMG_L2; jb.NCH[6] = NCH2; jb.so[6] = 0;  jb.nq[6] = 16;
    jb.W[7] = Wih2; jb.off[7] = WIMG_L2; jb.NCH[7] = NCH2; jb.so[7] = 16; jb.nq[7] = 16;
    { dim3 g(16, 128, 8); prep_w_all<<<g, 128>>>(jb, Wimg); }
    { dim3 g(8, TT); prep_x_kernel<<<g, 128>>>(x); }

    auto mkTask = [&](int L, int t) -> LTask {
        LTask T{};
        const int pv = t & 1, cu = pv ^ 1;
        float* hp = Hs + pv * SBUF; float* hc = Hs + cu * SBUF;
        float* cp = Cs + pv * SBUF; float* cc = Cs + cu * SBUF;
        T.t = t;
        if (L == 0) {
            T.wimg = Wimg + WIMG_L0; T.nch = NCH0;
            T.bp0 = himg_at(pv, 0); T.nq0 = 16;
            T.bp1 = Ximg + (size_t)t * 8 * B_CH; T.nq1 = 8;
            T.bp2 = himg_at(pv, 1); T.nq2 = 16;
            T.bias = b0;
            T.cprev = cp + 0 * BH; T.hprev = hp + 0 * BH;
            T.cout  = cc + 0 * BH; T.hout  = hc + 0 * BH;
            T.himg = himg_at(cu, 0); T.outp = nullptr;
        } else if (L == 1) {
            T.wimg = Wimg + WIMG_L1; T.nch = NCH1;
            T.bp0 = himg_at(pv, 1); T.nq0 = 16;
            T.bp1 = himg_at(cu, 0); T.nq1 = 16;
            T.bp2 = himg_at(pv, 2); T.nq2 = 16;
            T.bias = b1;
            T.cprev = cp + 1 * BH; T.hprev = hp + 1 * BH;
            T.cout  = cc + 1 * BH; T.hout  = hc + 1 * BH;
            T.himg = himg_at(cu, 1); T.outp = nullptr;
        } else {
            T.wimg = Wimg + WIMG_L2; T.nch = NCH2;
            T.bp0 = himg_at(pv, 2); T.nq0 = 16;
            T.bp1 = himg_at(cu, 1); T.nq1 = 16;
            T.bp2 = himg_at(cu, 1); T.nq2 = 0;     // unused
            T.bias = b2;
            T.cprev = cp + 2 * BH; T.hprev = hp + 2 * BH;
            T.cout  = cc + 2 * BH; T.hout  = hc + 2 * BH;
            T.himg = himg_at(cu, 2); T.outp = out + (size_t)t * BH;
        }
        return T;
    };

    // schedule: L0(0); { L1(t); [L2(t) + L0(t+1)] }; L2(255) last
    LTask dummy{};
    {
        LTask a = mkTask(0, 0);
        lstm_fused<<<128, 256, SMEM_DYN>>>(a, dummy, 0);
    }
    for (int t = 0; t < TT; t++) {
        LTask l1 = mkTask(1, t);
        lstm_fused<<<128, 256, SMEM_DYN>>>(l1, dummy, 0);

        LTask l2 = mkTask(2, t);
        if (t + 1 < TT) {
            LTask l0n = mkTask(0, t + 1);
            lstm_fused<<<128, 256, SMEM_DYN>>>(l2, l0n, 1);
        } else {
            lstm_fused<<<128, 256, SMEM_DYN>>>(l2, dummy, 0);
        }
    }

    finalize_kernel<<<(SBUF + 255) / 256, 256>>>(Hout, Cout);
}

// round 17
// speedup vs baseline: 1.4237x; 1.4237x over previous
#include <cuda_runtime.h>
#include <cuda_fp16.h>
#include <cstdint>

#define TT   256
#define BB   64
#define II   512
#define HH   1024
#define SBUF (3 * BB * HH)
#define BH   (BB * HH)

#define A_CH 4096      // weight chunk: 32j x 64k fp16, fragment order
#define B_CH 8192      // activation chunk: 64b x 64k fp16, fragment order
#define NCH0 40
#define NCH1 48
#define NCH2 32

#define WIMG_L0 0ULL
#define WIMG_L1 (WIMG_L0 + 128ULL * NCH0 * A_CH)
#define WIMG_L2 (WIMG_L1 + 128ULL * NCH1 * A_CH)
#define WIMG_TOT (WIMG_L2 + 128ULL * NCH2 * A_CH)

#define STG_BYTES 12288            // A 4KB + B 8KB per stage
#define NSTG 12                    // 6 pair-slots
#define SMEM_DYN (NSTG * STG_BYTES)   // 147456

__device__ __align__(16) char g_wimg[WIMG_TOT];                // ~63 MB
__device__ __align__(16) char g_ximg[(size_t)TT * 8 * B_CH];   // 16 MB
__device__ __align__(16) char g_himg[2][3][16 * B_CH];
__device__ float g_h[2 * SBUF];    // SORTED batch order
__device__ float g_c[2 * SBUF];
__device__ int   g_len[BB];        // sorted desc
__device__ int   g_perm[BB];       // sorted idx -> real b
__device__ int   g_mcnt[TT];       // m(t) = #(len > t)

__device__ __forceinline__ uint32_t smem_u32(const void* p) {
    uint32_t a;
    asm("{ .reg .u64 t; cvta.to.shared.u64 t, %1; cvt.u32.u64 %0, t; }" : "=r"(a) : "l"(p));
    return a;
}
__device__ __forceinline__ float sigf(float x) { return 1.0f / (1.0f + __expf(-x)); }
__device__ __forceinline__ uint32_t packh2(float a, float b) {
    __half2 h = __floats2half2_rn(a, b);
    return *(uint32_t*)&h;
}
__device__ __forceinline__ uint16_t h16bits(float v) {
    __half h = __float2half_rn(v);
    return *(uint16_t*)&h;
}

#define MMA(c, a, b) \
    asm volatile("mma.sync.aligned.m16n8k16.row.col.f32.f16.f16.f32 " \
        "{%0,%1,%2,%3}, {%4,%5,%6,%7}, {%8,%9}, {%0,%1,%2,%3};" \
        : "+f"((c)[0]), "+f"((c)[1]), "+f"((c)[2]), "+f"((c)[3]) \
        : "r"((a).x), "r"((a).y), "r"((a).z), "r"((a).w), "r"((b).x), "r"((b).y))

#define CPA16(dst, src) \
    asm volatile("cp.async.cg.shared.global [%0], [%1], 16;" :: "r"(dst), "l"(src))

// Fully-unrolled MMA body for NFB live 8-b blocks.
template<int NFB>
__device__ __forceinline__ void mma_body(
    const char* __restrict__ base, int jsub, int ksub, int bhalf, int lane,
    float (&acc)[4][4])
{
    const char* Ab = base + jsub * 512 + lane * 16;
    const char* Bb = base + 4096 + bhalf * 1024 + lane * 8;
#pragma unroll
    for (int kk = 0; kk < 2; kk++) {
        const int k16 = ksub * 2 + kk;
        const uint4 ah = *(const uint4*)(Ab + k16 * 1024);
#pragma unroll
        for (int nf = 0; nf < NFB; nf++) {
            const uint2 bh = *(const uint2*)(Bb + k16 * 2048 + nf * 256);
            MMA(acc[nf], ah, bh);
        }
    }
}

// ---------------- launch 1: sort lengths, perm, m(t) ----------------
__global__ void prep_sort(const void* lenbuf) {
    if (threadIdx.x != 0 || blockIdx.x != 0) return;
    const long long* L64 = (const long long*)lenbuf;
    const int*       L32 = (const int*)lenbuf;
    bool is64 = true;
    for (int b = 0; b < 32; b++) {
        long long v = L64[b];
        if (v < 0 || v > TT) { is64 = false; break; }
    }
    int len[BB], idx[BB];
    for (int b = 0; b < BB; b++) { len[b] = is64 ? (int)L64[b] : L32[b]; idx[b] = b; }
    for (int i = 1; i < BB; i++) {
        int lv = len[i], iv = idx[i], j = i - 1;
        while (j >= 0 && len[j] < lv) { len[j + 1] = len[j]; idx[j + 1] = idx[j]; j--; }
        len[j + 1] = lv; idx[j + 1] = iv;
    }
    for (int b = 0; b < BB; b++) { g_len[b] = len[b]; g_perm[b] = idx[b]; }
    for (int t = 0; t < TT; t++) {
        int m = 0;
        while (m < BB && len[m] > t) m++;
        g_mcnt[t] = m;
    }
}

// ---------------- launch 2: state copy + h0 images (sorted) ----------------
__global__ void __launch_bounds__(128) prep_misc(
    const float* __restrict__ h0, const float* __restrict__ c0)
{
    __shared__ float sa[64][68];
    const int q = blockIdx.x, o = blockIdx.y, tid = threadIdx.x;

    for (int i = (o * 16 + q) * 128 + tid; i < SBUF; i += 48 * 128) {
        int l = i >> 16, r = i & (BH - 1);
        int bs = r >> 10, n = r & (HH - 1);
        int src = l * BH + g_perm[bs] * HH + n;
        g_h[i] = h0[src]; g_c[i] = c0[src];
    }
    char* out = &g_himg[0][o][(size_t)q * B_CH];
    const int kb = q * 64;
#pragma unroll
    for (int r = 0; r < 8; r++) {
        int u = tid + 128 * r;
        int b = u >> 4, c4 = u & 15;
        const float4 v = *(const float4*)(h0 + ((size_t)o * BB + g_perm[b]) * HH + kb + c4 * 4);
        float* d = &sa[b][c4 * 4];
        d[0] = v.x; d[1] = v.y; d[2] = v.z; d[3] = v.w;
    }
    __syncthreads();
#pragma unroll
    for (int r = 0; r < 8; r++) {                  // 1024 8B units
        int u = tid + 128 * r;
        int lane = u & 31, rest = u >> 5;
        int nfrag = rest & 3, bgroup = (rest >> 2) & 1, k16 = rest >> 3;
        int g = lane >> 2, tig = lane & 3;
        int b = bgroup * 32 + nfrag * 8 + g;
        uint32_t regs[2];
#pragma unroll
        for (int kh = 0; kh < 2; kh++) {
            int k = k16 * 16 + 2 * tig + kh * 8;
            regs[kh] = packh2(sa[b][k], sa[b][k + 1]);
        }
        *(uint2*)(out + k16 * 2048 + bgroup * 1024 + nfrag * 256 + lane * 8)
            = make_uint2(regs[0], regs[1]);
    }
}

// ---------------- launch 3: weight images (all 8 jobs) ----------------
struct WJobs {
    const float* W[8];
    unsigned long long off[8];
    int NCH[8];
    int so[8];
    int nq[8];
};
__global__ void __launch_bounds__(128) prep_w_all(WJobs jb, char* __restrict__ wimg) {
    __shared__ float sw[64][36];
    const int jidx = blockIdx.z;
    const int q = blockIdx.x, jt = blockIdx.y, tid = threadIdx.x;
    if (q >= jb.nq[jidx]) return;
    const float* __restrict__ W = jb.W[jidx];
    char* out = wimg + jb.off[jidx] + ((size_t)jt * jb.NCH[jidx] + jb.so[jidx] + q) * A_CH;
    const int kb = q * 64;

#pragma unroll
    for (int r = 0; r < 4; r++) {
        int u = tid + 128 * r;
        int k = u >> 3, rem = u & 7, gate = rem >> 1, pair = rem & 1;
        const float4 v = *(const float4*)(W + (size_t)(kb + k) * 4096 + gate * 1024 + jt * 8 + pair * 4);
        float* d = &sw[k][gate * 8 + pair * 4];
        d[0] = v.x; d[1] = v.y; d[2] = v.z; d[3] = v.w;
    }
    __syncthreads();
#pragma unroll
    for (int r = 0; r < 2; r++) {                  // 256 16B units
        int u = tid + 128 * r;
        int lane = u & 31, rest = u >> 5;
        int jsub = rest & 1, k16 = rest >> 1;
        int g = lane >> 2, tig = lane & 3;
        uint32_t regs[4];
#pragma unroll
        for (int rg = 0; rg < 4; rg++) {
            int col = jsub * 16 + (rg & 1) * 8 + g;
            int kx  = k16 * 16 + 2 * tig + (rg >> 1) * 8;
            regs[rg] = packh2(sw[kx][col], sw[kx + 1][col]);
        }
        *(uint4*)(out + k16 * 1024 + jsub * 512 + lane * 16)
            = make_uint4(regs[0], regs[1], regs[2], regs[3]);
    }
}

// ---------------- launch 4: x images (sorted) ----------------
__global__ void __launch_bounds__(128) prep_x_kernel(const float* __restrict__ src) {
    __shared__ float sa[64][68];
    const int q = blockIdx.x, o = blockIdx.y, tid = threadIdx.x;
    const int kb = q * 64;
    char* out = g_ximg + ((size_t)o * 8 + q) * B_CH;

#pragma unroll
    for (int r = 0; r < 8; r++) {
        int u = tid + 128 * r;
        int b = u >> 4, c4 = u & 15;
        const float4 v = *(const float4*)(src + ((size_t)o * BB + g_perm[b]) * II + kb + c4 * 4);
        float* d = &sa[b][c4 * 4];
        d[0] = v.x; d[1] = v.y; d[2] = v.z; d[3] = v.w;
    }
    __syncthreads();
#pragma unroll
    for (int r = 0; r < 8; r++) {
        int u = tid + 128 * r;
        int lane = u & 31, rest = u >> 5;
        int nfrag = rest & 3, bgroup = (rest >> 2) & 1, k16 = rest >> 3;
        int g = lane >> 2, tig = lane & 3;
        int b = bgroup * 32 + nfrag * 8 + g;
        uint32_t regs[2];
#pragma unroll
        for (int kh = 0; kh < 2; kh++) {
            int k = k16 * 16 + 2 * tig + kh * 8;
            regs[kh] = packh2(sa[b][k], sa[b][k + 1]);
        }
        *(uint2*)(out + k16 * 2048 + bgroup * 1024 + nfrag * 256 + lane * 8)
            = make_uint2(regs[0], regs[1]);
    }
}

// ---------------- fp16 HMMA LSTM layer ----------------
// grid = 128 jt, 256 threads (8 warps). Warp: jsub = w>>2, ksub = (w>>1)&1, bhalf = w&1.
// Single fp16 GEMM (1 MMA per nf per k16). 12-stage pair pipeline (4 pairs in flight).
__global__ void __launch_bounds__(256, 1) lstm_mma_layer(
    const char* __restrict__ wimg, int nch,
    const char* b0p, int nq0, const char* b1p, int nq1, const char* b2p, int nq2,
    const float* __restrict__ bias,
    const float* __restrict__ cprev, const float* __restrict__ hprev,
    float* __restrict__ cout, float* __restrict__ hout,
    char* __restrict__ himg, float* __restrict__ outp, int t)
{
    extern __shared__ __align__(16) char sbuf[];   // 12 x [A 4KB | B 8KB]
    __shared__ float zsm[2][32][66];               // [ksub][jloc][b], padded

    const int tid = threadIdx.x;
    const int lane = tid & 31, w = tid >> 5;
    const int jt = blockIdx.x;
    const int jsub = w >> 2, ksub = (w >> 1) & 1, bhalf = w & 1;
    const uint32_t sb = smem_u32(sbuf);
    const char* achunks = wimg + (size_t)jt * nch * A_CH;

    const int m = g_mcnt[t];
    int nfb = (m - bhalf * 32 + 7) >> 3;
    if (nfb < 0) nfb = 0; if (nfb > 4) nfb = 4;
    const bool bact = (((tid >> 6) & 1) * 32 + ((tid >> 4) & 3) * 8) < m;

    float acc[4][4];
#pragma unroll
    for (int f = 0; f < 4; f++)
#pragma unroll
        for (int e = 0; e < 4; e++) acc[f][e] = 0.0f;

    auto bsrc = [&](int i) -> const char* {
        if (i < nq0) return b0p + (size_t)i * B_CH;
        i -= nq0;
        if (i < nq1) return b1p + (size_t)i * B_CH;
        i -= nq1;
        return b2p + (size_t)i * B_CH;
    };
    auto copy_chunk = [&](int ci) {                // no commit; caller groups
        const int stg = ci % NSTG;
        const char* sA = achunks + (size_t)ci * A_CH + tid * 16;
        uint32_t dA = sb + stg * STG_BYTES + tid * 16;
        CPA16(dA, sA);                             // A: 4096B = 256 thr x 16B
        if (bact) {
            const char* sB = bsrc(ci) + tid * 16;
            uint32_t dB = sb + stg * STG_BYTES + 4096 + tid * 16;
            CPA16(dB, sB);
            CPA16(dB + 4096, sB + 4096);
        }
    };
    auto copy_pair = [&](int p) {
        copy_chunk(2 * p);
        copy_chunk(2 * p + 1);
        asm volatile("cp.async.commit_group;" ::: "memory");
    };
    auto mma_sel = [&](int ci) {
        const char* base = sbuf + (ci % NSTG) * STG_BYTES;
        switch (nfb) {
            case 4: mma_body<4>(base, jsub, ksub, bhalf, lane, acc); break;
            case 3: mma_body<3>(base, jsub, ksub, bhalf, lane, acc); break;
            case 2: mma_body<2>(base, jsub, ksub, bhalf, lane, acc); break;
            case 1: mma_body<1>(base, jsub, ksub, bhalf, lane, acc); break;
            default: break;
        }
    };

    const int P = nch >> 1;                        // pairs (nch always even)
    copy_pair(0);
    if (P > 1) copy_pair(1);
    if (P > 2) copy_pair(2);
    if (P > 3) copy_pair(3);

    for (int p = 0; p < P; p++) {
        const int rem = P - 1 - p;
        if (rem >= 3)      asm volatile("cp.async.wait_group 3;" ::: "memory");
        else if (rem == 2) asm volatile("cp.async.wait_group 2;" ::: "memory");
        else if (rem == 1) asm volatile("cp.async.wait_group 1;" ::: "memory");
        else               asm volatile("cp.async.wait_group 0;" ::: "memory");
        __syncthreads();                           // pair p visible; pair p-2 slots long free

        if (p + 4 < P) copy_pair(p + 4);           // reuses slots of pair p-2 (consumed)

        mma_sel(2 * p);
        mma_sel(2 * p + 1);
    }
    __syncthreads();                               // all MMAs done

    // ---- exchange k-partials via zsm ----
    {
        const int g = lane >> 2, tig = lane & 3;
#pragma unroll
        for (int nf = 0; nf < 4; nf++) {
            const int bc = bhalf * 32 + nf * 8 + 2 * tig;
            zsm[ksub][jsub * 16 + g][bc]         = acc[nf][0];
            zsm[ksub][jsub * 16 + g][bc + 1]     = acc[nf][1];
            zsm[ksub][jsub * 16 + g + 8][bc]     = acc[nf][2];
            zsm[ksub][jsub * 16 + g + 8][bc + 1] = acc[nf][3];
        }
    }
    __syncthreads();

    // ---- gates + state update (sorted batch index) ----
    const int ni = tid >> 5;                       // 0..7
    const int bq = (tid & 31) * 2;                 // 0..62 (sorted index)
    const int ng = jt * 8 + ni;
    const float bfv = bias[ng], biv = bias[HH + ng], bov = bias[2 * HH + ng], bgv = bias[3 * HH + ng];

    const int k16h = (ng >> 4) & 3, kkh = ng & 15;
    const int tigh = (kkh >> 1) & 3, chh = kkh & 1, khalf = kkh >> 3;
    char* chb = himg + (size_t)(ng >> 6) * B_CH + k16h * 2048;
    const int inoff = khalf * 4 + chh * 2;

#pragma unroll
    for (int jb = 0; jb < 2; jb++) {
        const int b = bq + jb;                     // sorted index
        const float zf = zsm[0][0 + ni][b]  + zsm[1][0 + ni][b]  + bfv;
        const float zi = zsm[0][8 + ni][b]  + zsm[1][8 + ni][b]  + biv;
        const float zo = zsm[0][16 + ni][b] + zsm[1][16 + ni][b] + bov;
        const float zg = zsm[0][24 + ni][b] + zsm[1][24 + ni][b] + bgv;
        const int sidx = b * HH + ng;
        const float cold = cprev[sidx], hold = hprev[sidx];

        float c1 = sigf(zf) * cold + sigf(zi) * tanhf(zg);
        float h1 = sigf(zo) * tanhf(c1);
        if (!(t < g_len[b])) { c1 = cold; h1 = hold; }

        cout[sidx] = c1;
        hout[sidx] = h1;
        if (outp) outp[(size_t)g_perm[b] * HH + ng] = h1;

        const int bloc = b & 31;
        char* p = chb + (b >> 5) * 1024 + (bloc >> 3) * 256 + ((bloc & 7) * 4 + tigh) * 8 + inoff;
        *(uint16_t*)p = h16bits(h1);
    }
}

__global__ void finalize_kernel(float* __restrict__ Hout, float* __restrict__ Cout) {
    int i = blockIdx.x * blockDim.x + threadIdx.x;
    if (i < SBUF) {                                // t=255 odd -> cur in buf 0; un-permute
        int l = i >> 16, r = i & (BH - 1);
        int bs = r >> 10, n = r & (HH - 1);
        int dst = l * BH + g_perm[bs] * HH + n;
        Hout[dst] = g_h[i];
        Cout[dst] = g_c[i];
    }
}

// ---------------- host ----------------
extern "C" void kernel_launch(void* const* d_in, const int* in_sizes, int n_in,
                              void* d_out, int out_size) {
    const float* x    = (const float*)d_in[0];
    const void*  len  = d_in[1];
    const float* h0   = (const float*)d_in[2];
    const float* c0   = (const float*)d_in[3];
    const float* Wbh0 = (const float*)d_in[4];
    const float* Whh0 = (const float*)d_in[5];
    const float* Wth0 = (const float*)d_in[6];
    const float* b0   = (const float*)d_in[7];
    const float* Wbh1 = (const float*)d_in[8];
    const float* Whh1 = (const float*)d_in[9];
    const float* Wth1 = (const float*)d_in[10];
    const float* b1   = (const float*)d_in[11];
    const float* Wih2 = (const float*)d_in[12];
    const float* Whh2 = (const float*)d_in[13];
    const float* b2   = (const float*)d_in[14];

    float* out  = (float*)d_out;
    float* Hout = out + (size_t)TT * BB * HH;
    float* Cout = Hout + SBUF;

    void* p;
    cudaGetSymbolAddress(&p, g_wimg); char*  Wimg = (char*)p;
    cudaGetSymbolAddress(&p, g_ximg); char*  Ximg = (char*)p;
    cudaGetSymbolAddress(&p, g_himg); char*  Himg = (char*)p;
    cudaGetSymbolAddress(&p, g_h);    float* Hs   = (float*)p;
    cudaGetSymbolAddress(&p, g_c);    float* Cs   = (float*)p;

    const size_t HIMG_L = 16 * B_CH;
    auto himg_at = [&](int pp, int layer) { return Himg + ((size_t)pp * 3 + layer) * HIMG_L; };

    cudaFuncSetAttribute(lstm_mma_layer, cudaFuncAttributeMaxDynamicSharedMemorySize, SMEM_DYN);

    prep_sort<<<1, 32>>>(len);
    { dim3 g(16, 3); prep_misc<<<g, 128>>>(h0, c0); }
    WJobs jb;
    jb.W[0] = Whh0; jb.off[0] = WIMG_L0; jb.NCH[0] = NCH0; jb.so[0] = 0;  jb.nq[0] = 16;
    jb.W[1] = Wbh0; jb.off[1] = WIMG_L0; jb.NCH[1] = NCH0; jb.so[1] = 16; jb.nq[1] = 8;
    jb.W[2] = Wth0; jb.off[2] = WIMG_L0; jb.NCH[2] = NCH0; jb.so[2] = 24; jb.nq[2] = 16;
    jb.W[3] = Whh1; jb.off[3] = WIMG_L1; jb.NCH[3] = NCH1; jb.so[3] = 0;  jb.nq[3] = 16;
    jb.W[4] = Wbh1; jb.off[4] = WIMG_L1; jb.NCH[4] = NCH1; jb.so[4] = 16; jb.nq[4] = 16;
    jb.W[5] = Wth1; jb.off[5] = WIMG_L1; jb.NCH[5] = NCH1; jb.so[5] = 32; jb.nq[5] = 16;
    jb.W[6] = Whh2; jb.off[6] = WIMG_L2; jb.NCH[6] = NCH2; jb.so[6] = 0;  jb.nq[6] = 16;
    jb.W[7] = Wih2; jb.off[7] = WIMG_L2; jb.NCH[7] = NCH2; jb.so[7] = 16; jb.nq[7] = 16;
    { dim3 g(16, 128, 8); prep_w_all<<<g, 128>>>(jb, Wimg); }
    { dim3 g(8, TT); prep_x_kernel<<<g, 128>>>(x); }

    for (int t = 0; t < TT; t++) {
        const int pv = t & 1, cu = pv ^ 1;
        float* hp = Hs + pv * SBUF; float* hc = Hs + cu * SBUF;
        float* cp = Cs + pv * SBUF; float* cc = Cs + cu * SBUF;
        char* xt = Ximg + (size_t)t * 8 * B_CH;

        lstm_mma_layer<<<128, 256, SMEM_DYN>>>(
            Wimg + WIMG_L0, NCH0,
            himg_at(pv, 0), 16, xt, 8, himg_at(pv, 1), 16,
            b0, cp + 0 * BH, hp + 0 * BH,
            cc + 0 * BH, hc + 0 * BH,
            himg_at(cu, 0), nullptr, t);

        lstm_mma_layer<<<128, 256, SMEM_DYN>>>(
            Wimg + WIMG_L1, NCH1,
            himg_at(pv, 1), 16, himg_at(cu, 0), 16, himg_at(pv, 2), 16,
            b1, cp + 1 * BH, hp + 1 * BH,
            cc + 1 * BH, hc + 1 * BH,
            himg_at(cu, 1), nullptr, t);

        lstm_mma_layer<<<128, 256, SMEM_DYN>>>(
            Wimg + WIMG_L2, NCH2,
            himg_at(pv, 2), 16, himg_at(cu, 1), 16, nullptr, 0,
            b2, cp + 2 * BH, hp + 2 * BH,
            cc + 2 * BH, hc + 2 * BH,
            himg_at(cu, 2), out + (size_t)t * BH, t);
    }

    finalize_kernel<<<(SBUF + 255) / 256, 256>>>(Hout, Cout);
}